// round 10
// baseline (speedup 1.0000x reference)
#include <cuda_runtime.h>
#include <cuda_fp16.h>
#include <cstdint>

// ===========================================================================
// AxialAttention via mma.sync fp16 m16n8k16 + ldmatrix.
// CTA tile 128(M)x256(N), 8 warps as 2x4 of 64x64 warp tiles (LDSM:HMMA = 1:4),
// 3-stage cp.async, 1 CTA/SM (144KB smem). Softmax fused into GEMM epilogues.
//   QK  = Xh@[Wq;Wk]^T + [bq;bk]  [4096,2048] fp16
//   Vth = Wvh@Xh^T+bv             [1024,4096] fp16
//   P   = exp(Q@K^T/128) per batch, unnormalized fp16 (MODE 3) + rowsum atomics
//   Yh  = (P@Vt^T)/rowsum per batch, shuffle-stored (MODE 2)
//   out = Yh@Woh^T + bo (fp32)
// ===========================================================================

#define BK 64
#define ROW_BYTES 128
#define TM 128
#define TN 256
#define A_STG (TM * ROW_BYTES)        // 16 KB
#define B_STG (TN * ROW_BYTES)        // 32 KB
#define STAGES 3
#define SMEM_TOT (STAGES * (A_STG + B_STG))   // 144 KB -> 1 CTA/SM

// scratch
__device__ __half g_Xh[4096 * 1024];
__device__ __half g_Wh[4 * 1024 * 1024];
__device__ float  g_bqk[2048];
__device__ __half g_QK[4096 * 2048];
__device__ __half g_Vt[1024 * 4096];
__device__ __half g_P [2ll * 2048 * 2048];
__device__ __half g_Y [4096 * 1024];
__device__ float  g_rsum[2 * 2048];

__device__ __forceinline__ void mma_f16(float* d, const uint32_t* a,
                                        uint32_t b0, uint32_t b1) {
    asm volatile(
        "mma.sync.aligned.m16n8k16.row.col.f32.f16.f16.f32 "
        "{%0,%1,%2,%3}, {%4,%5,%6,%7}, {%8,%9}, {%0,%1,%2,%3};"
        : "+f"(d[0]), "+f"(d[1]), "+f"(d[2]), "+f"(d[3])
        : "r"(a[0]), "r"(a[1]), "r"(a[2]), "r"(a[3]), "r"(b0), "r"(b1));
}
__device__ __forceinline__ void ldsm4(uint32_t* r, uint32_t addr) {
    asm volatile("ldmatrix.sync.aligned.m8n8.x4.shared.b16 {%0,%1,%2,%3}, [%4];"
        : "=r"(r[0]), "=r"(r[1]), "=r"(r[2]), "=r"(r[3]) : "r"(addr));
}

#define CP_ASYNC(dst, src) \
    asm volatile("cp.async.cg.shared.global [%0], [%1], 16;" :: "r"(dst), \
                 "l"(__cvta_generic_to_global(src)))
#define CP_COMMIT() asm volatile("cp.async.commit_group;" ::: "memory")
#define CP_WAIT1()  asm volatile("cp.async.wait_group 1;" ::: "memory")

// ---------------------------------------------------------------------------
// MODE 0: plain store, bias by column.   MODE 1: plain store, bias by row.
// MODE 2: shuffle store (reference reshape), scaled by 1/rowsum[row].
// MODE 3: exp() store (unnormalized softmax), accumulate rowsum atomically.
// ---------------------------------------------------------------------------
template <int MODE, bool HALF_OUT>
__global__ void __launch_bounds__(256, 1) mma_gemm(
    const __half* __restrict__ A, int lda, long long sA,
    const __half* __restrict__ B, int ldb, long long sB,
    const float* __restrict__ bias, float* __restrict__ rowsum,
    void* __restrict__ Cv, int ldC, long long sC,
    int nch, float alpha)
{
    extern __shared__ __align__(128) char smc[];

    const __half* Ab = A + blockIdx.z * sA + (long long)blockIdx.y * TM * lda;
    const __half* Bb = B + blockIdx.z * sB + (long long)blockIdx.x * TN * ldb;

    int tid = threadIdx.x, lane = tid & 31, wid = tid >> 5;
    int gr = lane >> 2, qc = lane & 3;
    int mw = (wid >> 2) * 64, nw = (wid & 3) * 64;    // 2x4 warps of 64x64

    uint32_t sA32 = (uint32_t)__cvta_generic_to_shared(smc);
    uint32_t sB32 = sA32 + STAGES * A_STG;

    int t8 = lane & 7, half8 = (lane >> 3) & 1, cg = lane >> 4;
    uint32_t aRow[4], aX7[4], bRow[4], bX7[4];
#pragma unroll
    for (int mf = 0; mf < 4; mf++) {
        int r = mw + mf * 16 + half8 * 8 + t8;
        aRow[mf] = (uint32_t)r * ROW_BYTES;
        aX7[mf] = (uint32_t)(r & 7);
    }
#pragma unroll
    for (int p = 0; p < 4; p++) {
        int r = nw + p * 16 + half8 * 8 + t8;
        bRow[p] = (uint32_t)r * ROW_BYTES;
        bX7[p] = (uint32_t)(r & 7);
    }

    int lr = tid >> 3;            // 0..31
    int lc = tid & 7;             // 16B chunk

    float acc[4][8][4];
#pragma unroll
    for (int i = 0; i < 4; i++)
#pragma unroll
        for (int j = 0; j < 8; j++)
#pragma unroll
            for (int t = 0; t < 4; t++) acc[i][j][t] = 0.f;

    auto load_stage = [&](int ch, int st) {
        long long ko = (long long)ch * BK + lc * 8;
#pragma unroll
        for (int it = 0; it < 4; it++) {   // A: 128 rows
            int r = it * 32 + lr;
            uint32_t so = (uint32_t)(st * A_STG + r * ROW_BYTES +
                                     ((lc ^ (r & 7)) << 4));
            CP_ASYNC(sA32 + so, Ab + (long long)r * lda + ko);
        }
#pragma unroll
        for (int it = 0; it < 8; it++) {   // B: 256 rows
            int r = it * 32 + lr;
            uint32_t so = (uint32_t)(st * B_STG + r * ROW_BYTES +
                                     ((lc ^ (r & 7)) << 4));
            CP_ASYNC(sB32 + so, Bb + (long long)r * ldb + ko);
        }
    };

    load_stage(0, 0);
    CP_COMMIT();
    load_stage(1, 1);
    CP_COMMIT();

    int st = 0;
    for (int ch = 0; ch < nch; ch++) {
        CP_WAIT1();
        __syncthreads();
        if (ch + 2 < nch) load_stage(ch + 2, (ch + 2) % STAGES);
        CP_COMMIT();

        uint32_t stA = sA32 + st * A_STG;
        uint32_t stB = sB32 + st * B_STG;
        if (++st == STAGES) st = 0;
#pragma unroll
        for (int ks = 0; ks < 4; ks++) {
            uint32_t c = (uint32_t)(ks * 2 + cg);
            uint32_t af[4][4], bb[4][4];
#pragma unroll
            for (int mf = 0; mf < 4; mf++)
                ldsm4(af[mf], stA + aRow[mf] + ((c ^ aX7[mf]) << 4));
#pragma unroll
            for (int p = 0; p < 4; p++)
                ldsm4(bb[p], stB + bRow[p] + ((c ^ bX7[p]) << 4));
#pragma unroll
            for (int mf = 0; mf < 4; mf++)
#pragma unroll
                for (int nf = 0; nf < 8; nf++)
                    mma_f16(acc[mf][nf], af[mf],
                            bb[nf >> 1][nf & 1], bb[nf >> 1][2 + (nf & 1)]);
        }
    }

    // epilogue
#pragma unroll
    for (int mf = 0; mf < 4; mf++) {
        int row = blockIdx.y * TM + mw + mf * 16 + gr;
        float sum0 = 0.f, sum1 = 0.f;
        float inv0 = 1.f, inv1 = 1.f;
        if (MODE == 2) {
            const float* rs = rowsum + blockIdx.z * 2048;
            inv0 = 1.0f / rs[row];
            inv1 = 1.0f / rs[row + 8];
        }
#pragma unroll
        for (int nf = 0; nf < 8; nf++) {
            int col = blockIdx.x * TN + nw + nf * 8 + 2 * qc;
            float v0 = acc[mf][nf][0] * alpha;
            float v1 = acc[mf][nf][1] * alpha;
            float v2 = acc[mf][nf][2] * alpha;
            float v3 = acc[mf][nf][3] * alpha;
            if (MODE == 0 && bias) {
                float b0 = bias[col], b1 = bias[col + 1];
                v0 += b0; v1 += b1; v2 += b0; v3 += b1;
            }
            if (MODE == 1) {
                float b0 = bias[row], b1 = bias[row + 8];
                v0 += b0; v1 += b0; v2 += b1; v3 += b1;
            }
            if (MODE == 2) {
                v0 *= inv0; v1 *= inv0; v2 *= inv1; v3 *= inv1;
            }
            if (MODE == 3) {
                v0 = __expf(v0); v1 = __expf(v1);
                v2 = __expf(v2); v3 = __expf(v3);
                sum0 += v0 + v1; sum1 += v2 + v3;
            }
            long long o0, o1;
            if (MODE == 2) {
                int h = col >> 6, d0 = col & 63;
                o0 = (long long)(h * 128 + (row >> 4)) * 1024 + ((row & 15) << 6) + d0;
                int row2 = row + 8;
                o1 = (long long)(h * 128 + (row2 >> 4)) * 1024 + ((row2 & 15) << 6) + d0;
            } else {
                o0 = (long long)row * ldC + col;
                o1 = o0 + 8ll * ldC;
            }
            if (HALF_OUT) {
                __half* Cb = (__half*)Cv + blockIdx.z * sC;
                *(__half2*)(Cb + o0) = __floats2half2_rn(v0, v1);
                *(__half2*)(Cb + o1) = __floats2half2_rn(v2, v3);
            } else {
                float* Cb = (float*)Cv + blockIdx.z * sC;
                *(float2*)(Cb + o0) = make_float2(v0, v1);
                *(float2*)(Cb + o1) = make_float2(v2, v3);
            }
        }
        if (MODE == 3) {
            sum0 += __shfl_xor_sync(0xffffffffu, sum0, 1);
            sum0 += __shfl_xor_sync(0xffffffffu, sum0, 2);
            sum1 += __shfl_xor_sync(0xffffffffu, sum1, 1);
            sum1 += __shfl_xor_sync(0xffffffffu, sum1, 2);
            if (qc == 0) {
                float* rs = rowsum + blockIdx.z * 2048;
                atomicAdd(rs + row, sum0);
                atomicAdd(rs + row + 8, sum1);
            }
        }
    }
}

// ---------------------------------------------------------------------------
// fused fp32->fp16 conversion + bias concat + rowsum zeroing
// ---------------------------------------------------------------------------
__global__ __launch_bounds__(256) void f2h_all(
    const float4* __restrict__ x,
    const float4* __restrict__ w0, const float4* __restrict__ w1,
    const float4* __restrict__ w2, const float4* __restrict__ w3,
    const float* __restrict__ bq, const float* __restrict__ bk,
    __half* __restrict__ Xh, __half* __restrict__ Wh,
    float* __restrict__ bqk, float* __restrict__ rsum)
{
    int i = blockIdx.x * 256 + threadIdx.x;
    if (i < 2048) bqk[i] = (i < 1024) ? bq[i] : bk[i - 1024];
    if (i < 4096) rsum[i] = 0.f;
    const float4* src;
    __half* dst;
    if (i < (1 << 20)) { src = x + i; dst = Xh + (long long)i * 4; }
    else {
        int j = i - (1 << 20);
        int w = j >> 18, off = j & ((1 << 18) - 1);
        const float4* ws[4] = {w0, w1, w2, w3};
        src = ws[w] + off;
        dst = Wh + ((long long)w << 20) + (long long)off * 4;
    }
    float4 v = *src;
    __half2 h0 = __floats2half2_rn(v.x, v.y);
    __half2 h1 = __floats2half2_rn(v.z, v.w);
    *(uint2*)dst = make_uint2(*(uint32_t*)&h0, *(uint32_t*)&h1);
}

// ---------------------------------------------------------------------------
extern "C" void kernel_launch(void* const* d_in, const int* in_sizes, int n_in,
                              void* d_out, int out_size)
{
    const float* x  = (const float*)d_in[0];
    const float* bq = (const float*)d_in[2];
    const float* bk = (const float*)d_in[4];
    const float* bv = (const float*)d_in[6];
    const float* bo = (const float*)d_in[8];
    float* out = (float*)d_out;

    __half *Xh, *Wh, *QK, *Vt, *P, *Y;
    float *bqk, *rsum;
    cudaGetSymbolAddress((void**)&Xh,   g_Xh);
    cudaGetSymbolAddress((void**)&Wh,   g_Wh);
    cudaGetSymbolAddress((void**)&QK,   g_QK);
    cudaGetSymbolAddress((void**)&Vt,   g_Vt);
    cudaGetSymbolAddress((void**)&P,    g_P);
    cudaGetSymbolAddress((void**)&Y,    g_Y);
    cudaGetSymbolAddress((void**)&bqk,  g_bqk);
    cudaGetSymbolAddress((void**)&rsum, g_rsum);

    cudaFuncSetAttribute(mma_gemm<0, true>,  cudaFuncAttributeMaxDynamicSharedMemorySize, SMEM_TOT);
    cudaFuncSetAttribute(mma_gemm<0, false>, cudaFuncAttributeMaxDynamicSharedMemorySize, SMEM_TOT);
    cudaFuncSetAttribute(mma_gemm<1, true>,  cudaFuncAttributeMaxDynamicSharedMemorySize, SMEM_TOT);
    cudaFuncSetAttribute(mma_gemm<2, true>,  cudaFuncAttributeMaxDynamicSharedMemorySize, SMEM_TOT);
    cudaFuncSetAttribute(mma_gemm<3, true>,  cudaFuncAttributeMaxDynamicSharedMemorySize, SMEM_TOT);

    f2h_all<<<8192, 256>>>((const float4*)x,
                           (const float4*)d_in[1], (const float4*)d_in[3],
                           (const float4*)d_in[5], (const float4*)d_in[7],
                           bq, bk, Xh, Wh, bqk, rsum);

    dim3 blk(256);

    // QK = Xh @ [Wq;Wk]^T + [bq;bk] -> fp16 [4096,2048]
    mma_gemm<0, true><<<dim3(8, 32, 1), blk, SMEM_TOT>>>(
        Xh, 1024, 0, Wh, 1024, 0, bqk, nullptr, QK, 2048, 0, 16, 1.f);
    // Vt = Wv @ Xh^T + bv (bias by row=e) -> fp16 [1024,4096]
    mma_gemm<1, true><<<dim3(16, 8, 1), blk, SMEM_TOT>>>(
        Wh + 2097152, 1024, 0, Xh, 1024, 0, bv, nullptr, Vt, 4096, 0, 16, 1.f);
    // P = exp(Q @ K^T / 128) per batch -> fp16 [2,2048,2048], rowsums accumulated
    mma_gemm<3, true><<<dim3(8, 16, 2), blk, SMEM_TOT>>>(
        QK, 2048, 2048ll * 2048, QK + 1024, 2048, 2048ll * 2048,
        nullptr, rsum, P, 2048, 2048ll * 2048, 16, 1.f / 128.f);
    // Y = (P @ Vt^T) / rowsum per batch, shuffled -> fp16 [4096,1024]
    mma_gemm<2, true><<<dim3(4, 16, 2), blk, SMEM_TOT>>>(
        P, 2048, 2048ll * 2048, Vt, 4096, 2048,
        nullptr, rsum, Y, 1024, 2048ll * 1024, 32, 1.f);
    // out = Y @ Wo^T + bo -> fp32
    mma_gemm<0, false><<<dim3(4, 32, 1), blk, SMEM_TOT>>>(
        Y, 1024, 0, Wh + 3145728, 1024, 0, bo, nullptr, out, 1024, 0, 16, 1.f);
}